// round 2
// baseline (speedup 1.0000x reference)
#include <cuda_runtime.h>

// Problem constants (fixed shapes)
#define BB 4
#define SS 1024
#define DD 1024
#define HH 16
#define DHH 64
#define RR (BB*SS)        // 4096 rows
#define NELEM (RR*DD)     // 4194304

// Scratch (device globals: no allocation allowed)
__device__ float d_g[NELEM];    // GEMM output (pre-BN)
__device__ float d_h0[NELEM];   // ping
__device__ float d_h1[NELEM];   // pong
__device__ float g_sum[DD];
__device__ float g_sqsum[DD];
__device__ float g_nmul[DD];
__device__ float g_nadd[DD];

// ---------------------------------------------------------------------------
// GEMM: d_g[r,o] = (sum_i x[r,i] * W[o,i]) * scale[o]
// 64x64 tile, BK=16, 256 threads, 4x4 per-thread microtile
// ---------------------------------------------------------------------------
__global__ __launch_bounds__(256) void gemm_kernel(const float* __restrict__ x,
                                                   const float* __restrict__ W,
                                                   const float* __restrict__ scale) {
    __shared__ __align__(16) float As[16 * 68];
    __shared__ __align__(16) float Bs[16 * 68];
    const int tid = threadIdx.x;
    const int tx = tid & 15, ty = tid >> 4;
    const int r0 = blockIdx.y * 64, o0 = blockIdx.x * 64;
    float acc[4][4] = {};
    for (int k0 = 0; k0 < DD; k0 += 16) {
#pragma unroll
        for (int i = 0; i < 4; i++) {
            int idx = tid + i * 256;
            int m = idx >> 4, k = idx & 15;
            As[k * 68 + m] = x[(size_t)(r0 + m) * DD + k0 + k];
            Bs[k * 68 + m] = W[(size_t)(o0 + m) * DD + k0 + k];
        }
        __syncthreads();
#pragma unroll
        for (int k = 0; k < 16; k++) {
            float4 a4 = *(const float4*)(As + k * 68 + ty * 4);
            float4 b4 = *(const float4*)(Bs + k * 68 + tx * 4);
            float av[4] = {a4.x, a4.y, a4.z, a4.w};
            float bv[4] = {b4.x, b4.y, b4.z, b4.w};
#pragma unroll
            for (int i = 0; i < 4; i++)
#pragma unroll
                for (int j = 0; j < 4; j++)
                    acc[i][j] += av[i] * bv[j];
        }
        __syncthreads();
    }
    float4 sc4 = *(const float4*)(scale + o0 + tx * 4);
    float sc[4] = {sc4.x, sc4.y, sc4.z, sc4.w};
#pragma unroll
    for (int i = 0; i < 4; i++) {
        size_t row = (size_t)(r0 + ty * 4 + i) * DD + o0 + tx * 4;
        float4 ov = make_float4(acc[i][0] * sc[0], acc[i][1] * sc[1],
                                acc[i][2] * sc[2], acc[i][3] * sc[3]);
        *(float4*)(d_g + row) = ov;
    }
}

// ---------------------------------------------------------------------------
// BatchNorm statistics
// ---------------------------------------------------------------------------
__global__ __launch_bounds__(256) void zero_stats_kernel() {
    int i = blockIdx.x * 256 + threadIdx.x;
    if (i < DD) { g_sum[i] = 0.f; g_sqsum[i] = 0.f; }
}

__global__ __launch_bounds__(256) void stats_partial_kernel() {
    int r0 = blockIdx.x * 64;
    float s[4] = {0.f, 0.f, 0.f, 0.f};
    float ss[4] = {0.f, 0.f, 0.f, 0.f};
    for (int r = 0; r < 64; r++) {
        const float* row = d_g + (size_t)(r0 + r) * DD;
#pragma unroll
        for (int c = 0; c < 4; c++) {
            float v = row[threadIdx.x + c * 256];
            s[c] += v; ss[c] += v * v;
        }
    }
#pragma unroll
    for (int c = 0; c < 4; c++) {
        atomicAdd(&g_sum[threadIdx.x + c * 256], s[c]);
        atomicAdd(&g_sqsum[threadIdx.x + c * 256], ss[c]);
    }
}

__global__ __launch_bounds__(256) void finalize_kernel(const float* __restrict__ gamma,
                                                       const float* __restrict__ beta) {
    int f = blockIdx.x * 256 + threadIdx.x;
    if (f < DD) {
        float mu = g_sum[f] * (1.f / RR);
        float var = g_sqsum[f] * (1.f / RR) - mu * mu;
        float rs = rsqrtf(var + 1e-5f);
        float gm = gamma[f] * rs;
        g_nmul[f] = gm;
        g_nadd[f] = beta[f] - gm * mu;
    }
}

// ---------------------------------------------------------------------------
// Elementwise epilogue: BN apply + ReLU + dropout mask + residual + biases
// ---------------------------------------------------------------------------
__global__ __launch_bounds__(256) void post_kernel(const float* __restrict__ mask,
                                                   const float* __restrict__ resid,
                                                   const float* __restrict__ attn,
                                                   const float* __restrict__ pos) {
    int i = blockIdx.x * 256 + threadIdx.x;   // float4 index, NELEM/4 total
    int fb = (i & 255) * 4;                   // feature index of first lane
    float4 gv = *(const float4*)(d_g + (size_t)i * 4);
    float4 mk = ((const float4*)mask)[i];
    float4 rv = ((const float4*)resid)[i];
    float4 av = ((const float4*)attn)[i];
    float4 pv = ((const float4*)pos)[i];
    float g[4] = {gv.x, gv.y, gv.z, gv.w};
    float m[4] = {mk.x, mk.y, mk.z, mk.w};
    float r[4] = {rv.x, rv.y, rv.z, rv.w};
    float a[4] = {av.x, av.y, av.z, av.w};
    float p[4] = {pv.x, pv.y, pv.z, pv.w};
    float o[4];
#pragma unroll
    for (int c = 0; c < 4; c++) {
        float h = g[c] * g_nmul[fb + c] + g_nadd[fb + c];
        h = fmaxf(h, 0.f) * m[c];
        o[c] = h + r[c] + a[c] + p[c];
    }
    *(float4*)(d_h0 + (size_t)i * 4) = make_float4(o[0], o[1], o[2], o[3]);
}

// ---------------------------------------------------------------------------
// Flash attention stage: h_out = h_in + MHA(h_in + qb, kb, vb)
// Block: (b,h) x q-tile-of-64; 256 threads; 4q x 4k per-thread microtiles.
// Smem: Qt[d][q] / Kt[d][k] transposed (conflict-free LDS.128 in QK),
//       Vs[k][d], Ps[q][k].
// ---------------------------------------------------------------------------
__global__ __launch_bounds__(256) void attn_kernel(const float* __restrict__ h_in,
                                                   const float* __restrict__ qb,
                                                   const float* __restrict__ kb,
                                                   const float* __restrict__ vb,
                                                   float* __restrict__ h_out) {
    extern __shared__ __align__(16) float sm[];
    float* Qt = sm;                 // [64 d][68]
    float* Kt = sm + 64 * 68;       // [64 d][68]
    float* Vs = sm + 2 * 64 * 68;   // [64 k][68]
    float* Ps = sm + 3 * 64 * 68;   // [64 q][68]

    const int tid = threadIdx.x;
    const int tx = tid & 15, ty = tid >> 4;
    const int tx4 = tx * 4, ty4 = ty * 4;
    const int bh = blockIdx.x;
    const int b = bh >> 4, hd = bh & 15;
    const int q0 = blockIdx.y * 64;
    const size_t base = (size_t)b * (SS * DD) + (size_t)hd * DHH;

    // Load Q tile (h + query bias), transposed to [d][q]
    for (int idx = tid; idx < 64 * 64; idx += 256) {
        int qi = idx >> 6, d = idx & 63;
        size_t g = base + (size_t)(q0 + qi) * DD + d;
        Qt[d * 68 + qi] = h_in[g] + qb[g];
    }

    float m[4], l[4], o[4][4];
#pragma unroll
    for (int i = 0; i < 4; i++) {
        m[i] = -1e30f; l[i] = 0.f;
#pragma unroll
        for (int j = 0; j < 4; j++) o[i][j] = 0.f;
    }
    __syncthreads();

    for (int kt = 0; kt < 16; kt++) {
        const int k0 = kt * 64;
        // Load K (transposed [d][k]) and V ([k][d]) tiles
        for (int idx = tid; idx < 64 * 64; idx += 256) {
            int r = idx >> 6, d = idx & 63;
            size_t g = base + (size_t)(k0 + r) * DD + d;
            Kt[d * 68 + r] = kb[g];
            Vs[r * 68 + d] = vb[g];
        }
        __syncthreads();

        // S = Q K^T  (4q x 4k per thread)
        float s[4][4];
#pragma unroll
        for (int i = 0; i < 4; i++)
#pragma unroll
            for (int j = 0; j < 4; j++) s[i][j] = 0.f;
#pragma unroll 8
        for (int d = 0; d < 64; d++) {
            float4 q4 = *(const float4*)(Qt + d * 68 + ty4);
            float4 k4 = *(const float4*)(Kt + d * 68 + tx4);
            float qa[4] = {q4.x, q4.y, q4.z, q4.w};
            float ka[4] = {k4.x, k4.y, k4.z, k4.w};
#pragma unroll
            for (int i = 0; i < 4; i++)
#pragma unroll
                for (int j = 0; j < 4; j++)
                    s[i][j] += qa[i] * ka[j];
        }

        // Online softmax per q-row (16 lanes own one row)
#pragma unroll
        for (int i = 0; i < 4; i++) {
            float rowm = -1e30f;
#pragma unroll
            for (int j = 0; j < 4; j++) {
                s[i][j] *= 0.125f;   // 1/sqrt(64)
                rowm = fmaxf(rowm, s[i][j]);
            }
#pragma unroll
            for (int off = 1; off < 16; off <<= 1)
                rowm = fmaxf(rowm, __shfl_xor_sync(0xffffffffu, rowm, off));
            float newm = fmaxf(m[i], rowm);
            float alpha = __expf(m[i] - newm);
            float p[4], rs = 0.f;
#pragma unroll
            for (int j = 0; j < 4; j++) { p[j] = __expf(s[i][j] - newm); rs += p[j]; }
#pragma unroll
            for (int off = 1; off < 16; off <<= 1)
                rs += __shfl_xor_sync(0xffffffffu, rs, off);
            l[i] = l[i] * alpha + rs;
            m[i] = newm;
#pragma unroll
            for (int j = 0; j < 4; j++) o[i][j] *= alpha;
            *(float4*)(Ps + (ty4 + i) * 68 + tx4) = make_float4(p[0], p[1], p[2], p[3]);
        }
        __syncthreads();

        // O += P V  (4q x 4d per thread)
#pragma unroll 8
        for (int k = 0; k < 64; k++) {
            float4 v4 = *(const float4*)(Vs + k * 68 + tx4);
            float va[4] = {v4.x, v4.y, v4.z, v4.w};
#pragma unroll
            for (int i = 0; i < 4; i++) {
                float pv = Ps[(ty4 + i) * 68 + k];
#pragma unroll
                for (int j = 0; j < 4; j++) o[i][j] += pv * va[j];
            }
        }
        __syncthreads();
    }

    // Residual add + write
#pragma unroll
    for (int i = 0; i < 4; i++) {
        float inv = 1.f / l[i];
        size_t g = base + (size_t)(q0 + ty4 + i) * DD + tx4;
        float4 hv = *(const float4*)(h_in + g);
        float4 ov = make_float4(hv.x + o[i][0] * inv, hv.y + o[i][1] * inv,
                                hv.z + o[i][2] * inv, hv.w + o[i][3] * inv);
        *(float4*)(h_out + g) = ov;
    }
}

// ---------------------------------------------------------------------------
extern "C" void kernel_launch(void* const* d_in, const int* in_sizes, int n_in,
                              void* d_out, int out_size) {
    const float* x     = (const float*)d_in[0];
    const float* W     = (const float*)d_in[1];
    const float* scale = (const float*)d_in[2];
    const float* gamma = (const float*)d_in[3];
    const float* beta  = (const float*)d_in[4];
    const float* mask  = (const float*)d_in[5];
    const float* resid = (const float*)d_in[6];
    const float* attnb = (const float*)d_in[7];
    const float* posb  = (const float*)d_in[8];
    float* out = (float*)d_out;

    const int ATTN_SMEM = 4 * 64 * 68 * 4;   // 69632 bytes
    cudaFuncSetAttribute(attn_kernel, cudaFuncAttributeMaxDynamicSharedMemorySize, ATTN_SMEM);

    float *h0, *h1;
    cudaGetSymbolAddress((void**)&h0, d_h0);
    cudaGetSymbolAddress((void**)&h1, d_h1);

    zero_stats_kernel<<<4, 256>>>();
    gemm_kernel<<<dim3(16, 64), 256>>>(x, W, scale);
    stats_partial_kernel<<<64, 256>>>();
    finalize_kernel<<<4, 256>>>(gamma, beta);
    post_kernel<<<4096, 256>>>(mask, resid, attnb, posb);

    dim3 ag(BB * HH, SS / 64);   // (64, 16)
    const float* cur = h0;
    float* pong[2] = {h1, h0};
    for (int st = 0; st < 6; st++) {
        const float* q = (const float*)d_in[9 + 3 * st];
        const float* k = (const float*)d_in[10 + 3 * st];
        const float* v = (const float*)d_in[11 + 3 * st];
        float* dst = (st == 5) ? out : pong[st & 1];
        attn_kernel<<<ag, 256, ATTN_SMEM>>>(cur, q, k, v, dst);
        cur = dst;
    }
}

// round 5
// speedup vs baseline: 2.2696x; 2.2696x over previous
#include <cuda_runtime.h>
#include <cstdint>

// Problem constants (fixed shapes)
#define BB 4
#define SS 1024
#define DD 1024
#define HH 16
#define DHH 64
#define RR (BB*SS)        // 4096 rows
#define NELEM (RR*DD)     // 4194304

// Scratch (device globals: no allocation allowed)
__device__ float d_g[NELEM];    // GEMM output (pre-BN)
__device__ float d_h0[NELEM];   // ping
__device__ float d_h1[NELEM];   // pong
__device__ float g_sum[DD];
__device__ float g_sqsum[DD];
__device__ float g_nmul[DD];
__device__ float g_nadd[DD];

// ---------------------------------------------------------------------------
// tf32 helpers
// ---------------------------------------------------------------------------
__device__ __forceinline__ uint32_t f2tf(float x) {
    uint32_t r; asm("cvt.rna.tf32.f32 %0, %1;" : "=r"(r) : "f"(x)); return r;
}

__device__ __forceinline__ void mma8(float* c,
                                     uint32_t a0, uint32_t a1, uint32_t a2, uint32_t a3,
                                     uint32_t b0, uint32_t b1) {
    asm volatile("mma.sync.aligned.m16n8k8.row.col.f32.tf32.tf32.f32 "
                 "{%0,%1,%2,%3},{%4,%5,%6,%7},{%8,%9},{%0,%1,%2,%3};"
                 : "+f"(c[0]), "+f"(c[1]), "+f"(c[2]), "+f"(c[3])
                 : "r"(a0), "r"(a1), "r"(a2), "r"(a3), "r"(b0), "r"(b1));
}

// ---------------------------------------------------------------------------
// GEMM: d_g[r,o] = (sum_i x[r,i] * W[o,i]) * scale[o]   (fp32)
// ---------------------------------------------------------------------------
__global__ __launch_bounds__(256) void gemm_kernel(const float* __restrict__ x,
                                                   const float* __restrict__ W,
                                                   const float* __restrict__ scale) {
    __shared__ __align__(16) float As[16 * 68];
    __shared__ __align__(16) float Bs[16 * 68];
    const int tid = threadIdx.x;
    const int tx = tid & 15, ty = tid >> 4;
    const int r0 = blockIdx.y * 64, o0 = blockIdx.x * 64;
    float acc[4][4] = {};
    for (int k0 = 0; k0 < DD; k0 += 16) {
#pragma unroll
        for (int i = 0; i < 4; i++) {
            int idx = tid + i * 256;
            int m = idx >> 4, k = idx & 15;
            As[k * 68 + m] = x[(size_t)(r0 + m) * DD + k0 + k];
            Bs[k * 68 + m] = W[(size_t)(o0 + m) * DD + k0 + k];
        }
        __syncthreads();
#pragma unroll
        for (int k = 0; k < 16; k++) {
            float4 a4 = *(const float4*)(As + k * 68 + ty * 4);
            float4 b4 = *(const float4*)(Bs + k * 68 + tx * 4);
            float av[4] = {a4.x, a4.y, a4.z, a4.w};
            float bv[4] = {b4.x, b4.y, b4.z, b4.w};
#pragma unroll
            for (int i = 0; i < 4; i++)
#pragma unroll
                for (int j = 0; j < 4; j++)
                    acc[i][j] += av[i] * bv[j];
        }
        __syncthreads();
    }
    float4 sc4 = *(const float4*)(scale + o0 + tx * 4);
    float sc[4] = {sc4.x, sc4.y, sc4.z, sc4.w};
#pragma unroll
    for (int i = 0; i < 4; i++) {
        size_t row = (size_t)(r0 + ty * 4 + i) * DD + o0 + tx * 4;
        float4 ov = make_float4(acc[i][0] * sc[0], acc[i][1] * sc[1],
                                acc[i][2] * sc[2], acc[i][3] * sc[3]);
        *(float4*)(d_g + row) = ov;
    }
}

// ---------------------------------------------------------------------------
// BatchNorm statistics
// ---------------------------------------------------------------------------
__global__ __launch_bounds__(256) void zero_stats_kernel() {
    int i = blockIdx.x * 256 + threadIdx.x;
    if (i < DD) { g_sum[i] = 0.f; g_sqsum[i] = 0.f; }
}

__global__ __launch_bounds__(256) void stats_partial_kernel() {
    int r0 = blockIdx.x * 64;
    float s[4] = {0.f, 0.f, 0.f, 0.f};
    float ss[4] = {0.f, 0.f, 0.f, 0.f};
    for (int r = 0; r < 64; r++) {
        const float* row = d_g + (size_t)(r0 + r) * DD;
#pragma unroll
        for (int c = 0; c < 4; c++) {
            float v = row[threadIdx.x + c * 256];
            s[c] += v; ss[c] += v * v;
        }
    }
#pragma unroll
    for (int c = 0; c < 4; c++) {
        atomicAdd(&g_sum[threadIdx.x + c * 256], s[c]);
        atomicAdd(&g_sqsum[threadIdx.x + c * 256], ss[c]);
    }
}

__global__ __launch_bounds__(256) void finalize_kernel(const float* __restrict__ gamma,
                                                       const float* __restrict__ beta) {
    int f = blockIdx.x * 256 + threadIdx.x;
    if (f < DD) {
        float mu = g_sum[f] * (1.f / RR);
        float var = g_sqsum[f] * (1.f / RR) - mu * mu;
        float rs = rsqrtf(var + 1e-5f);
        float gm = gamma[f] * rs;
        g_nmul[f] = gm;
        g_nadd[f] = beta[f] - gm * mu;
    }
}

// ---------------------------------------------------------------------------
// Elementwise epilogue
// ---------------------------------------------------------------------------
__global__ __launch_bounds__(256) void post_kernel(const float* __restrict__ mask,
                                                   const float* __restrict__ resid,
                                                   const float* __restrict__ attn,
                                                   const float* __restrict__ pos) {
    int i = blockIdx.x * 256 + threadIdx.x;
    int fb = (i & 255) * 4;
    float4 gv = *(const float4*)(d_g + (size_t)i * 4);
    float4 mk = ((const float4*)mask)[i];
    float4 rv = ((const float4*)resid)[i];
    float4 av = ((const float4*)attn)[i];
    float4 pv = ((const float4*)pos)[i];
    float g[4] = {gv.x, gv.y, gv.z, gv.w};
    float m[4] = {mk.x, mk.y, mk.z, mk.w};
    float r[4] = {rv.x, rv.y, rv.z, rv.w};
    float a[4] = {av.x, av.y, av.z, av.w};
    float p[4] = {pv.x, pv.y, pv.z, pv.w};
    float o[4];
#pragma unroll
    for (int c = 0; c < 4; c++) {
        float h = g[c] * g_nmul[fb + c] + g_nadd[fb + c];
        h = fmaxf(h, 0.f) * m[c];
        o[c] = h + r[c] + a[c] + p[c];
    }
    *(float4*)(d_h0 + (size_t)i * 4) = make_float4(o[0], o[1], o[2], o[3]);
}

// ---------------------------------------------------------------------------
// Flash attention stage with tf32 tensor-core MMA.
//   h_out = h_in + MHA(h_in + qb, kb, vb)
// Block: (b,h) x q-tile of 128. 256 threads = 8 warps; warp w owns q-rows
// [w*16, w*16+16). Each warp computes its FULL 16x64 S stripe, does softmax
// entirely in-warp (rows never split across warps), then its own 16x64 PV.
// ---------------------------------------------------------------------------
#define QT 128
#define KT 64
#define LDA 68

__global__ __launch_bounds__(256, 2) void attn_kernel(const float* __restrict__ h_in,
                                                      const float* __restrict__ qb,
                                                      const float* __restrict__ kb,
                                                      const float* __restrict__ vb,
                                                      float* __restrict__ h_out) {
    extern __shared__ uint32_t smu[];
    uint32_t* Qs = smu;                  // [128][LDA] tf32
    uint32_t* Ks = Qs + QT * LDA;        // [64][LDA]  (key-major: [k][d])
    uint32_t* Vs = Ks + KT * LDA;        // [64][LDA]  ([k][d])
    uint32_t* Ps = Vs + KT * LDA;        // [128][LDA] (warp-private stripes)

    const int tid = threadIdx.x;
    const int lane = tid & 31, w = tid >> 5;
    const int wq = w * 16;                 // warp q offset within tile
    const int r4 = lane >> 2, c4 = lane & 3;

    const int bh = blockIdx.x;
    const int b = bh >> 4, hd = bh & 15;
    const int q0 = blockIdx.y * QT;
    const size_t base = (size_t)b * (SS * DD) + (size_t)hd * DHH;

    // Load Q tile (h + query bias), convert to tf32
#pragma unroll
    for (int it = 0; it < (QT * DHH) / 4 / 256; it++) {   // 8 iters
        int idx = tid + it * 256;                          // float4 index
        int qi = idx >> 4, d4 = (idx & 15) * 4;
        size_t g = base + (size_t)(q0 + qi) * DD + d4;
        float4 a = *(const float4*)(h_in + g);
        float4 q4 = *(const float4*)(qb + g);
        uint32_t* dst = Qs + qi * LDA + d4;
        dst[0] = f2tf(a.x + q4.x); dst[1] = f2tf(a.y + q4.y);
        dst[2] = f2tf(a.z + q4.z); dst[3] = f2tf(a.w + q4.w);
    }

    // Accumulators: o[n][4] over 8 n-tiles (d cols n*8 + 2*c4 + {0,1}),
    // rows r4 (regs 0,1) and r4+8 (regs 2,3). mx/l per owned row (2).
    float o[8][4];
    float mx[2], l[2];
#pragma unroll
    for (int n = 0; n < 8; n++)
#pragma unroll
        for (int j = 0; j < 4; j++) o[n][j] = 0.f;
    mx[0] = mx[1] = -1e30f; l[0] = l[1] = 0.f;
    __syncthreads();

    for (int kt = 0; kt < SS / KT; kt++) {
        const int k0 = kt * KT;
        // Load K, V tiles, convert to tf32
#pragma unroll
        for (int it = 0; it < 4; it++) {
            int idx = tid + it * 256;
            int r = idx >> 4, d4 = (idx & 15) * 4;
            size_t g = base + (size_t)(k0 + r) * DD + d4;
            float4 kv = *(const float4*)(kb + g);
            float4 vv = *(const float4*)(vb + g);
            uint32_t* dk = Ks + r * LDA + d4;
            dk[0] = f2tf(kv.x); dk[1] = f2tf(kv.y); dk[2] = f2tf(kv.z); dk[3] = f2tf(kv.w);
            uint32_t* dv = Vs + r * LDA + d4;
            dv[0] = f2tf(vv.x); dv[1] = f2tf(vv.y); dv[2] = f2tf(vv.z); dv[3] = f2tf(vv.w);
        }
        __syncthreads();

        // S = Q K^T : warp stripe 16q x 64k (8 n-tiles of m16n8k8, k-dim = d)
        float s[8][4];
#pragma unroll
        for (int n = 0; n < 8; n++)
#pragma unroll
            for (int j = 0; j < 4; j++) s[n][j] = 0.f;

#pragma unroll
        for (int k8 = 0; k8 < 8; k8++) {
            const int kb8 = k8 * 8;
            const uint32_t* qp = Qs + (wq + r4) * LDA + kb8 + c4;
            uint32_t a0 = qp[0], a1 = qp[8 * LDA], a2 = qp[4], a3 = qp[8 * LDA + 4];
#pragma unroll
            for (int n = 0; n < 8; n++) {
                const uint32_t* kp = Ks + (n * 8 + r4) * LDA + kb8 + c4;
                mma8(s[n], a0, a1, a2, a3, kp[0], kp[4]);
            }
        }

        // Online softmax (rows fully within this warp: cols 0..63)
#pragma unroll
        for (int h = 0; h < 2; h++) {
            float rm = -1e30f;
#pragma unroll
            for (int n = 0; n < 8; n++) {
                s[n][h * 2]     *= 0.125f;   // 1/sqrt(64)
                s[n][h * 2 + 1] *= 0.125f;
                rm = fmaxf(rm, fmaxf(s[n][h * 2], s[n][h * 2 + 1]));
            }
            rm = fmaxf(rm, __shfl_xor_sync(0xffffffffu, rm, 1));
            rm = fmaxf(rm, __shfl_xor_sync(0xffffffffu, rm, 2));
            float nm = fmaxf(mx[h], rm);
            float alpha = __expf(mx[h] - nm);
            mx[h] = nm;
            float rs = 0.f;
            uint32_t* prow = Ps + (wq + h * 8 + r4) * LDA + c4 * 2;
#pragma unroll
            for (int n = 0; n < 8; n++) {
                float p0 = __expf(s[n][h * 2] - nm);
                float p1 = __expf(s[n][h * 2 + 1] - nm);
                rs += p0 + p1;
                prow[n * 8]     = f2tf(p0);
                prow[n * 8 + 1] = f2tf(p1);
            }
            rs += __shfl_xor_sync(0xffffffffu, rs, 1);
            rs += __shfl_xor_sync(0xffffffffu, rs, 2);
            l[h] = l[h] * alpha + rs;
#pragma unroll
            for (int n = 0; n < 8; n++) {
                o[n][h * 2]     *= alpha;
                o[n][h * 2 + 1] *= alpha;
            }
        }
        __syncwarp();   // P stripe is warp-private: warp-level visibility suffices

        // O += P V : warp stripe 16q x 64d, inner dim = 64 key slots
#pragma unroll
        for (int k8 = 0; k8 < 8; k8++) {
            const int kb8 = k8 * 8;
            const uint32_t* pp = Ps + (wq + r4) * LDA + kb8 + c4;
            uint32_t a0 = pp[0], a1 = pp[8 * LDA], a2 = pp[4], a3 = pp[8 * LDA + 4];
#pragma unroll
            for (int n = 0; n < 8; n++) {
                const uint32_t* vp = Vs + (kb8 + c4) * LDA + n * 8 + r4;
                mma8(o[n], a0, a1, a2, a3, vp[0], vp[4 * LDA]);
            }
        }
        __syncthreads();   // all warps done with Ks/Vs before next tile load
    }

    // Finalize: divide by l, add residual h_in, write out
#pragma unroll
    for (int h = 0; h < 2; h++) {
        float inv = 1.f / l[h];
        int row = q0 + wq + h * 8 + r4;
#pragma unroll
        for (int n = 0; n < 8; n++) {
            size_t g = base + (size_t)row * DD + n * 8 + c4 * 2;
            float2 hv = *(const float2*)(h_in + g);
            float2 ov = make_float2(hv.x + o[n][h * 2] * inv,
                                    hv.y + o[n][h * 2 + 1] * inv);
            *(float2*)(h_out + g) = ov;
        }
    }
}

// ---------------------------------------------------------------------------
extern "C" void kernel_launch(void* const* d_in, const int* in_sizes, int n_in,
                              void* d_out, int out_size) {
    const float* x     = (const float*)d_in[0];
    const float* W     = (const float*)d_in[1];
    const float* scale = (const float*)d_in[2];
    const float* gamma = (const float*)d_in[3];
    const float* beta  = (const float*)d_in[4];
    const float* mask  = (const float*)d_in[5];
    const float* resid = (const float*)d_in[6];
    const float* attnb = (const float*)d_in[7];
    const float* posb  = (const float*)d_in[8];
    float* out = (float*)d_out;

    const int ATTN_SMEM = (QT * LDA + KT * LDA + KT * LDA + QT * LDA) * 4;  // 104448 B
    cudaFuncSetAttribute(attn_kernel, cudaFuncAttributeMaxDynamicSharedMemorySize, ATTN_SMEM);

    float *h0, *h1;
    cudaGetSymbolAddress((void**)&h0, d_h0);
    cudaGetSymbolAddress((void**)&h1, d_h1);

    zero_stats_kernel<<<4, 256>>>();
    gemm_kernel<<<dim3(16, 64), 256>>>(x, W, scale);
    stats_partial_kernel<<<64, 256>>>();
    finalize_kernel<<<4, 256>>>(gamma, beta);
    post_kernel<<<4096, 256>>>(mask, resid, attnb, posb);

    dim3 ag(BB * HH, SS / QT);   // (64, 8)
    const float* cur = h0;
    float* pong[2] = {h1, h0};
    for (int st = 0; st < 6; st++) {
        const float* q = (const float*)d_in[9 + 3 * st];
        const float* k = (const float*)d_in[10 + 3 * st];
        const float* v = (const float*)d_in[11 + 3 * st];
        float* dst = (st == 5) ? out : pong[st & 1];
        attn_kernel<<<ag, 256, ATTN_SMEM>>>(cur, q, k, v, dst);
        cur = dst;
    }
}

// round 8
// speedup vs baseline: 4.8695x; 2.1456x over previous
#include <cuda_runtime.h>
#include <cuda_fp16.h>
#include <cstdint>

// Problem constants (fixed shapes)
#define BB 4
#define SS 1024
#define DD 1024
#define HH 16
#define DHH 64
#define RR (BB*SS)        // 4096 rows
#define NELEM (RR*DD)     // 4194304

// Scratch (device globals: no allocation allowed)
__device__ float d_g[NELEM];    // GEMM output (pre-BN)
__device__ float d_h0[NELEM];   // ping
__device__ float d_h1[NELEM];   // pong
__device__ float g_sum[DD];
__device__ float g_sqsum[DD];
__device__ float g_nmul[DD];
__device__ float g_nadd[DD];

// ---------------------------------------------------------------------------
// fp16 helpers
// ---------------------------------------------------------------------------
__device__ __forceinline__ uint32_t f2h2(float a, float b) {
    __half2 h = __floats2half2_rn(a, b);
    return *(uint32_t*)&h;
}

__device__ __forceinline__ void mma16(float* c,
                                      uint32_t a0, uint32_t a1, uint32_t a2, uint32_t a3,
                                      uint32_t b0, uint32_t b1) {
    asm volatile("mma.sync.aligned.m16n8k16.row.col.f32.f16.f16.f32 "
                 "{%0,%1,%2,%3},{%4,%5,%6,%7},{%8,%9},{%0,%1,%2,%3};"
                 : "+f"(c[0]), "+f"(c[1]), "+f"(c[2]), "+f"(c[3])
                 : "r"(a0), "r"(a1), "r"(a2), "r"(a3), "r"(b0), "r"(b1));
}

__device__ __forceinline__ void ldsm4t(uint32_t& r0, uint32_t& r1, uint32_t& r2, uint32_t& r3,
                                       uint32_t addr) {
    asm volatile("ldmatrix.sync.aligned.m8n8.x4.trans.shared.b16 {%0,%1,%2,%3}, [%4];"
                 : "=r"(r0), "=r"(r1), "=r"(r2), "=r"(r3) : "r"(addr));
}

__device__ __forceinline__ uint32_t smem_u32(const void* p) {
    uint32_t a;
    asm("{ .reg .u64 t; cvta.to.shared.u64 t, %1; cvt.u32.u64 %0, t; }" : "=r"(a) : "l"(p));
    return a;
}

// ---------------------------------------------------------------------------
// GEMM: d_g[r,o] = (sum_i x[r,i] * W[o,i]) * scale[o]   (fp16 MMA, fp32 acc)
// CTA tile 128r x 64o, k-tiles of 64; 8 warps, each 16r x 64o stripe.
// ---------------------------------------------------------------------------
#define LDW 36   // uint32 (half2) row stride

__global__ __launch_bounds__(256) void gemm_kernel(const float* __restrict__ x,
                                                   const float* __restrict__ W,
                                                   const float* __restrict__ scale) {
    __shared__ __align__(16) uint32_t Xs[128 * LDW];
    __shared__ __align__(16) uint32_t Ws[64 * LDW];
    const int tid = threadIdx.x;
    const int lane = tid & 31, w = tid >> 5;
    const int wq = w * 16;
    const int r4 = lane >> 2, c4 = lane & 3;
    const int r0 = blockIdx.y * 128, o0 = blockIdx.x * 64;

    float acc[8][4];
#pragma unroll
    for (int n = 0; n < 8; n++)
#pragma unroll
        for (int j = 0; j < 4; j++) acc[n][j] = 0.f;

    for (int k0 = 0; k0 < DD; k0 += 64) {
#pragma unroll
        for (int it = 0; it < 8; it++) {             // Xs: 128x64 halves
            int idx = tid + it * 256;
            int r = idx >> 4, d4 = (idx & 15) * 4;
            float4 v = *(const float4*)(x + (size_t)(r0 + r) * DD + k0 + d4);
            uint32_t* dst = Xs + r * LDW + (idx & 15) * 2;
            dst[0] = f2h2(v.x, v.y); dst[1] = f2h2(v.z, v.w);
        }
#pragma unroll
        for (int it = 0; it < 4; it++) {             // Ws: 64x64
            int idx = tid + it * 256;
            int r = idx >> 4, d4 = (idx & 15) * 4;
            float4 v = *(const float4*)(W + (size_t)(o0 + r) * DD + k0 + d4);
            uint32_t* dst = Ws + r * LDW + (idx & 15) * 2;
            dst[0] = f2h2(v.x, v.y); dst[1] = f2h2(v.z, v.w);
        }
        __syncthreads();

#pragma unroll
        for (int k16 = 0; k16 < 4; k16++) {
            const uint32_t* xp = Xs + (wq + r4) * LDW + k16 * 8 + c4;
            uint32_t a0 = xp[0], a1 = xp[8 * LDW], a2 = xp[4], a3 = xp[8 * LDW + 4];
#pragma unroll
            for (int n = 0; n < 8; n++) {
                const uint32_t* wp = Ws + (n * 8 + r4) * LDW + k16 * 8 + c4;
                mma16(acc[n], a0, a1, a2, a3, wp[0], wp[4]);
            }
        }
        __syncthreads();
    }

#pragma unroll
    for (int h = 0; h < 2; h++) {
        int row = r0 + wq + h * 8 + r4;
#pragma unroll
        for (int n = 0; n < 8; n++) {
            float2 sc = *(const float2*)(scale + o0 + n * 8 + c4 * 2);
            float2 ov = make_float2(acc[n][h * 2] * sc.x, acc[n][h * 2 + 1] * sc.y);
            *(float2*)(d_g + (size_t)row * DD + o0 + n * 8 + c4 * 2) = ov;
        }
    }
}

// ---------------------------------------------------------------------------
// BatchNorm statistics
// ---------------------------------------------------------------------------
__global__ __launch_bounds__(256) void zero_stats_kernel() {
    int i = blockIdx.x * 256 + threadIdx.x;
    if (i < DD) { g_sum[i] = 0.f; g_sqsum[i] = 0.f; }
}

__global__ __launch_bounds__(256) void stats_partial_kernel() {
    int r0 = blockIdx.x * 64;
    float s[4] = {0.f, 0.f, 0.f, 0.f};
    float ss[4] = {0.f, 0.f, 0.f, 0.f};
    for (int r = 0; r < 64; r++) {
        const float* row = d_g + (size_t)(r0 + r) * DD;
#pragma unroll
        for (int c = 0; c < 4; c++) {
            float v = row[threadIdx.x + c * 256];
            s[c] += v; ss[c] += v * v;
        }
    }
#pragma unroll
    for (int c = 0; c < 4; c++) {
        atomicAdd(&g_sum[threadIdx.x + c * 256], s[c]);
        atomicAdd(&g_sqsum[threadIdx.x + c * 256], ss[c]);
    }
}

__global__ __launch_bounds__(256) void finalize_kernel(const float* __restrict__ gamma,
                                                       const float* __restrict__ beta) {
    int f = blockIdx.x * 256 + threadIdx.x;
    if (f < DD) {
        float mu = g_sum[f] * (1.f / RR);
        float var = g_sqsum[f] * (1.f / RR) - mu * mu;
        float rs = rsqrtf(var + 1e-5f);
        float gm = gamma[f] * rs;
        g_nmul[f] = gm;
        g_nadd[f] = beta[f] - gm * mu;
    }
}

// ---------------------------------------------------------------------------
// Elementwise epilogue
// ---------------------------------------------------------------------------
__global__ __launch_bounds__(256) void post_kernel(const float* __restrict__ mask,
                                                   const float* __restrict__ resid,
                                                   const float* __restrict__ attn,
                                                   const float* __restrict__ pos) {
    int i = blockIdx.x * 256 + threadIdx.x;
    int fb = (i & 255) * 4;
    float4 gv = *(const float4*)(d_g + (size_t)i * 4);
    float4 mk = ((const float4*)mask)[i];
    float4 rv = ((const float4*)resid)[i];
    float4 av = ((const float4*)attn)[i];
    float4 pv = ((const float4*)pos)[i];
    float g[4] = {gv.x, gv.y, gv.z, gv.w};
    float m[4] = {mk.x, mk.y, mk.z, mk.w};
    float r[4] = {rv.x, rv.y, rv.z, rv.w};
    float a[4] = {av.x, av.y, av.z, av.w};
    float p[4] = {pv.x, pv.y, pv.z, pv.w};
    float o[4];
#pragma unroll
    for (int c = 0; c < 4; c++) {
        float h = g[c] * g_nmul[fb + c] + g_nadd[fb + c];
        h = fmaxf(h, 0.f) * m[c];
        o[c] = h + r[c] + a[c] + p[c];
    }
    *(float4*)(d_h0 + (size_t)i * 4) = make_float4(o[0], o[1], o[2], o[3]);
}

// ---------------------------------------------------------------------------
// Flash attention stage, fp16 MMA (m16n8k16, fp32 accum).
//   h_out = h_in + MHA(h_in + qb, kb, vb)
// Block: (b,h) x q-tile 128. 8 warps; warp w owns q-rows [w*16, w*16+16).
// Q/K/P in smem as half2 words (stride 36 w). V row-major [key][d] halves;
// its B-fragments come from ldmatrix.x4.trans.
// ---------------------------------------------------------------------------
#define QT 128
#define KT 64
#define LDH 36                       // uint32 (half2) row stride
#define VROWB (LDH * 4)              // V row stride in BYTES = 144  (fixed!)

__global__ __launch_bounds__(256, 2) void attn_kernel(const float* __restrict__ h_in,
                                                      const float* __restrict__ qb,
                                                      const float* __restrict__ kb,
                                                      const float* __restrict__ vb,
                                                      float* __restrict__ h_out) {
    extern __shared__ __align__(16) uint32_t smu[];
    uint32_t* Qs = smu;                  // [128][LDH]
    uint32_t* Ks = Qs + QT * LDH;        // [64][LDH]   [key][d]
    uint32_t* Vs = Ks + KT * LDH;        // [64][LDH]   [key][d]
    uint32_t* Ps = Vs + KT * LDH;        // [128][LDH]  warp-private stripes

    const int tid = threadIdx.x;
    const int lane = tid & 31, w = tid >> 5;
    const int wq = w * 16;
    const int r4 = lane >> 2, c4 = lane & 3;

    const int bh = blockIdx.x;
    const int b = bh >> 4, hd = bh & 15;
    const int q0 = blockIdx.y * QT;
    const size_t base = (size_t)b * (SS * DD) + (size_t)hd * DHH;

    // ldmatrix.x4.trans lane addressing: lanes 0-15 -> key rows 0-15, d cols 0-7;
    // lanes 16-31 -> same keys, d cols 8-15 (16-byte offset).
    const uint32_t vbase = smem_u32(Vs) + (lane & 15) * VROWB + (lane >> 4) * 16;

    // Load Q tile (h + query bias) -> half2
#pragma unroll
    for (int it = 0; it < 8; it++) {
        int idx = tid + it * 256;
        int qi = idx >> 4, d4 = (idx & 15) * 4;
        size_t g = base + (size_t)(q0 + qi) * DD + d4;
        float4 a = *(const float4*)(h_in + g);
        float4 q4 = *(const float4*)(qb + g);
        uint32_t* dst = Qs + qi * LDH + (idx & 15) * 2;
        dst[0] = f2h2(a.x + q4.x, a.y + q4.y);
        dst[1] = f2h2(a.z + q4.z, a.w + q4.w);
    }

    float o[8][4];
    float mx[2], l[2];
#pragma unroll
    for (int n = 0; n < 8; n++)
#pragma unroll
        for (int j = 0; j < 4; j++) o[n][j] = 0.f;
    mx[0] = mx[1] = -1e30f; l[0] = l[1] = 0.f;
    __syncthreads();

    for (int kt = 0; kt < SS / KT; kt++) {
        const int k0 = kt * KT;
#pragma unroll
        for (int it = 0; it < 4; it++) {
            int idx = tid + it * 256;
            int r = idx >> 4, d4 = (idx & 15) * 4;
            size_t g = base + (size_t)(k0 + r) * DD + d4;
            float4 kv = *(const float4*)(kb + g);
            float4 vv = *(const float4*)(vb + g);
            uint32_t* dk = Ks + r * LDH + (idx & 15) * 2;
            dk[0] = f2h2(kv.x, kv.y); dk[1] = f2h2(kv.z, kv.w);
            uint32_t* dv = Vs + r * LDH + (idx & 15) * 2;
            dv[0] = f2h2(vv.x, vv.y); dv[1] = f2h2(vv.z, vv.w);
        }
        __syncthreads();

        // S = Q K^T : 16q x 64k per warp, inner dim d=64 (4 k16 steps)
        float s[8][4];
#pragma unroll
        for (int n = 0; n < 8; n++)
#pragma unroll
            for (int j = 0; j < 4; j++) s[n][j] = 0.f;

#pragma unroll
        for (int k16 = 0; k16 < 4; k16++) {
            const uint32_t* qp = Qs + (wq + r4) * LDH + k16 * 8 + c4;
            uint32_t a0 = qp[0], a1 = qp[8 * LDH], a2 = qp[4], a3 = qp[8 * LDH + 4];
#pragma unroll
            for (int n = 0; n < 8; n++) {
                const uint32_t* kp = Ks + (n * 8 + r4) * LDH + k16 * 8 + c4;
                mma16(s[n], a0, a1, a2, a3, kp[0], kp[4]);
            }
        }

        // Online softmax (rows fully in-warp)
#pragma unroll
        for (int h = 0; h < 2; h++) {
            float rm = -1e30f;
#pragma unroll
            for (int n = 0; n < 8; n++) {
                s[n][h * 2]     *= 0.125f;   // 1/sqrt(64)
                s[n][h * 2 + 1] *= 0.125f;
                rm = fmaxf(rm, fmaxf(s[n][h * 2], s[n][h * 2 + 1]));
            }
            rm = fmaxf(rm, __shfl_xor_sync(0xffffffffu, rm, 1));
            rm = fmaxf(rm, __shfl_xor_sync(0xffffffffu, rm, 2));
            float nm = fmaxf(mx[h], rm);
            float alpha = __expf(mx[h] - nm);
            mx[h] = nm;
            float rs = 0.f;
            uint32_t* prow = Ps + (wq + h * 8 + r4) * LDH + c4;
#pragma unroll
            for (int n = 0; n < 8; n++) {
                float p0 = __expf(s[n][h * 2] - nm);
                float p1 = __expf(s[n][h * 2 + 1] - nm);
                rs += p0 + p1;
                prow[n * 4] = f2h2(p0, p1);
            }
            rs += __shfl_xor_sync(0xffffffffu, rs, 1);
            rs += __shfl_xor_sync(0xffffffffu, rs, 2);
            l[h] = l[h] * alpha + rs;
#pragma unroll
            for (int n = 0; n < 8; n++) {
                o[n][h * 2]     *= alpha;
                o[n][h * 2 + 1] *= alpha;
            }
        }
        __syncwarp();   // P stripe is warp-private

        // O += P V : inner dim 64 keys (4 k16 steps); V fragments via ldmatrix.trans
#pragma unroll
        for (int k16 = 0; k16 < 4; k16++) {
            const uint32_t* pp = Ps + (wq + r4) * LDH + k16 * 8 + c4;
            uint32_t a0 = pp[0], a1 = pp[8 * LDH], a2 = pp[4], a3 = pp[8 * LDH + 4];
            const uint32_t va = vbase + k16 * 16 * VROWB;
#pragma unroll
            for (int n = 0; n < 8; n += 2) {
                uint32_t b0, b1, b2, b3;
                ldsm4t(b0, b1, b2, b3, va + n * 16);
                mma16(o[n],     a0, a1, a2, a3, b0, b1);
                mma16(o[n + 1], a0, a1, a2, a3, b2, b3);
            }
        }
        __syncthreads();
    }

    // Finalize: divide by l, add residual h_in, write out
#pragma unroll
    for (int h = 0; h < 2; h++) {
        float inv = 1.f / l[h];
        int row = q0 + wq + h * 8 + r4;
#pragma unroll
        for (int n = 0; n < 8; n++) {
            size_t g = base + (size_t)row * DD + n * 8 + c4 * 2;
            float2 hv = *(const float2*)(h_in + g);
            float2 ov = make_float2(hv.x + o[n][h * 2] * inv,
                                    hv.y + o[n][h * 2 + 1] * inv);
            *(float2*)(h_out + g) = ov;
        }
    }
}

// ---------------------------------------------------------------------------
extern "C" void kernel_launch(void* const* d_in, const int* in_sizes, int n_in,
                              void* d_out, int out_size) {
    const float* x     = (const float*)d_in[0];
    const float* W     = (const float*)d_in[1];
    const float* scale = (const float*)d_in[2];
    const float* gamma = (const float*)d_in[3];
    const float* beta  = (const float*)d_in[4];
    const float* mask  = (const float*)d_in[5];
    const float* resid = (const float*)d_in[6];
    const float* attnb = (const float*)d_in[7];
    const float* posb  = (const float*)d_in[8];
    float* out = (float*)d_out;

    const int ATTN_SMEM = (QT * LDH + KT * LDH + KT * LDH + QT * LDH) * 4;  // 55296 B
    cudaFuncSetAttribute(attn_kernel, cudaFuncAttributeMaxDynamicSharedMemorySize, ATTN_SMEM);

    float *h0, *h1;
    cudaGetSymbolAddress((void**)&h0, d_h0);
    cudaGetSymbolAddress((void**)&h1, d_h1);

    zero_stats_kernel<<<4, 256>>>();
    gemm_kernel<<<dim3(16, 32), 256>>>(x, W, scale);
    stats_partial_kernel<<<64, 256>>>();
    finalize_kernel<<<4, 256>>>(gamma, beta);
    post_kernel<<<4096, 256>>>(mask, resid, attnb, posb);

    dim3 ag(BB * HH, SS / QT);   // (64, 8)
    const float* cur = h0;
    float* pong[2] = {h1, h0};
    for (int st = 0; st < 6; st++) {
        const float* q = (const float*)d_in[9 + 3 * st];
        const float* k = (const float*)d_in[10 + 3 * st];
        const float* v = (const float*)d_in[11 + 3 * st];
        float* dst = (st == 5) ? out : pong[st & 1];
        attn_kernel<<<ag, 256, ATTN_SMEM>>>(cur, q, k, v, dst);
        cur = dst;
    }
}